// round 3
// baseline (speedup 1.0000x reference)
#include <cuda_runtime.h>
#include <cstdint>
#include <math.h>

#define NPTS    4096
#define MAXQ    32768             // B=8 * 4096
#define THREADS 256
#define QPAIRS  4                 // packed query pairs per thread (8 queries)
#define QPT     (QPAIRS * 2)
#define QPB     (THREADS * QPT)   // 2048 queries per block
#define JCHUNK  256               // candidates per block
#define NCHUNK  (NPTS / JCHUNK)   // 16
#define NGROUP  32                // argmin recovery granularity
#define NGROUPS (JCHUNK / NGROUP) // 8
#define NRED    256

typedef unsigned long long ull;

// Per (dir, chunk, query): (fkey(e_min) << 32) | group_start_index_within_batch
__device__ ull   g_part[2][NCHUNK][MAXQ];
__device__ float g_bsum[NRED];

__device__ __forceinline__ ull fma2(ull a, ull b, ull c) {
    ull d;
    asm("fma.rn.f32x2 %0, %1, %2, %3;" : "=l"(d) : "l"(a), "l"(b), "l"(c));
    return d;
}
__device__ __forceinline__ ull pack2(float lo, float hi) {
    ull d;
    asm("mov.b64 %0, {%1, %2};" : "=l"(d) : "f"(lo), "f"(hi));
    return d;
}
__device__ __forceinline__ ull dup2(float v) { return pack2(v, v); }
__device__ __forceinline__ float lof(ull v) { return __uint_as_float((unsigned int)v); }
__device__ __forceinline__ float hif(ull v) { return __uint_as_float((unsigned int)(v >> 32)); }

// Order-preserving float -> uint32 (handles negatives; e can be negative).
__device__ __forceinline__ unsigned int fkey(float f) {
    unsigned int b = __float_as_uint(f);
    return (b & 0x80000000u) ? ~b : (b | 0x80000000u);
}

// NN kernel: tracks min over candidates of e = |c|^2 - 2<q,c>  (d = |q|^2 + e,
// same argmin). Two queries per f32x2 lane; candidates broadcast from smem.
// Inner loop per candidate: 3 FFMA2 (fma pipe) + 2 FMNMX (alu pipe) per packed
// pair. Argmin index is NOT tracked per-candidate; only the best group of 32
// is recorded and the exact index is recovered later (bit-exact rescan).
__global__ void __launch_bounds__(THREADS, 4) nn_kernel(
    const float* __restrict__ X1, const float* __restrict__ X2)
{
    __shared__ ull tile[JCHUNK][4];   // per candidate: {xx, yy, zz, ww=|c|^2}

    const int dir   = blockIdx.z;              // 0: Q=X1,C=X2   1: Q=X2,C=X1
    const float* __restrict__ Q = dir ? X2 : X1;
    const float* __restrict__ C = dir ? X1 : X2;

    const int tid   = threadIdx.x;
    const int chunk = blockIdx.x;              // 0..NCHUNK-1
    const int qbase = blockIdx.y * QPB;
    const int batch = qbase / NPTS;            // QPB divides NPTS
    const int jloc  = chunk * JCHUNK;          // candidate base within batch

    {
        const float* p = C + (size_t)(batch * NPTS + jloc + tid) * 6;
        float x = p[0], y = p[1], z = p[2];
        tile[tid][0] = dup2(x);
        tile[tid][1] = dup2(y);
        tile[tid][2] = dup2(z);
        tile[tid][3] = dup2(fmaf(x, x, fmaf(y, y, z * z)));
    }
    __syncthreads();

    // Queries with -2 folded into coordinates.
    ull nx[QPAIRS], ny[QPAIRS], nz[QPAIRS];
    int q0[QPAIRS];
#pragma unroll
    for (int p = 0; p < QPAIRS; p++) {
        q0[p] = qbase + (p * THREADS + tid) * 2;
        const float* a = Q + (size_t)q0[p] * 6;
        const float* b = a + 6;
        nx[p] = pack2(-2.0f * a[0], -2.0f * b[0]);
        ny[p] = pack2(-2.0f * a[1], -2.0f * b[1]);
        nz[p] = pack2(-2.0f * a[2], -2.0f * b[2]);
    }

    float beste[QPT];
    int   bestg[QPT];
#pragma unroll
    for (int q = 0; q < QPT; q++) { beste[q] = 3.4e38f; bestg[q] = 0; }

    const ull* tp = &tile[0][0];
#pragma unroll 1
    for (int g = 0; g < NGROUPS; g++) {
        float gmin[QPT];
#pragma unroll
        for (int q = 0; q < QPT; q++) gmin[q] = 3.4e38f;

#pragma unroll 8
        for (int cc = 0; cc < NGROUP; cc++) {
            ulonglong2 cA = *(const ulonglong2*)(tp);       // xx, yy
            ulonglong2 cB = *(const ulonglong2*)(tp + 2);   // zz, ww
            tp += 4;
#pragma unroll
            for (int p = 0; p < QPAIRS; p++) {
                ull t = fma2(nz[p], cB.x, cB.y);            // z*cz + |c|^2
                t = fma2(ny[p], cA.y, t);
                t = fma2(nx[p], cA.x, t);                   // e for 2 queries
                gmin[2 * p]     = fminf(gmin[2 * p],     lof(t));  // FMNMX (alu)
                gmin[2 * p + 1] = fminf(gmin[2 * p + 1], hif(t));
            }
        }
#pragma unroll
        for (int q = 0; q < QPT; q++)
            if (gmin[q] < beste[q]) { beste[q] = gmin[q]; bestg[q] = g; }
    }

#pragma unroll
    for (int p = 0; p < QPAIRS; p++) {
#pragma unroll
        for (int h = 0; h < 2; h++) {
            int qq = 2 * p + h;
            unsigned int start = (unsigned int)(jloc + bestg[qq] * NGROUP);
            g_part[dir][chunk][q0[p] + h] =
                ((ull)fkey(beste[qq]) << 32) | start;
        }
    }
}

__device__ __forceinline__ float normal_diff2(const float* __restrict__ a,
                                              const float* __restrict__ b) {
    float ax = a[0], ay = a[1], az = a[2];
    float bx = b[0], by = b[1], bz = b[2];
    float ia = 1.0f / fmaxf(sqrtf(fmaf(ax, ax, fmaf(ay, ay, az * az))), 1e-12f);
    float ib = 1.0f / fmaxf(sqrtf(fmaf(bx, bx, fmaf(by, by, bz * bz))), 1e-12f);
    float dx = ax * ia - bx * ib;
    float dy = ay * ia - by * ib;
    float dz = az * ia - bz * ib;
    return fmaf(dx, dx, fmaf(dy, dy, dz * dz));
}

// Merge chunk records per query (u64 min: min e, tie -> smallest start =
// first occurrence), rescan the winning 32-candidate group with the
// bit-identical scalar FMA chain to recover the exact argmin index, then
// compute dist + normal terms and block-reduce.
__global__ void __launch_bounds__(THREADS) merge_kernel(
    const float* __restrict__ X1, const float* __restrict__ X2, int nq)
{
    int gi = blockIdx.x * blockDim.x + threadIdx.x;   // 0 .. 2*nq-1
    float acc = 0.0f;
    if (gi < 2 * nq) {
        int dir = gi >= nq;
        int q   = dir ? gi - nq : gi;
        int batch = q / NPTS;

        ull best = ~0ull;
#pragma unroll
        for (int ch = 0; ch < NCHUNK; ch++) {
            ull v = g_part[dir][ch][q];
            best = (v < best) ? v : best;
        }
        int start = (int)(best & 0xFFFFFFFFull);      // within batch

        const float* __restrict__ Qb = dir ? X2 : X1;
        const float* __restrict__ Cb = dir ? X1 : X2;
        const float* qp = Qb + (size_t)q * 6;
        float qx = qp[0], qy = qp[1], qz = qp[2];
        float nxs = -2.0f * qx, nys = -2.0f * qy, nzs = -2.0f * qz;

        const float* cbase = Cb + (size_t)(batch * NPTS + start) * 6;
        float be = 3.4e38f;
        int   bi = 0;
#pragma unroll 4
        for (int j = 0; j < NGROUP; j++) {
            const float* c = cbase + j * 6;
            float cx = c[0], cy = c[1], cz = c[2];
            float cw = fmaf(cx, cx, fmaf(cy, cy, cz * cz));
            float t  = fmaf(nxs, cx, fmaf(nys, cy, fmaf(nzs, cz, cw)));
            if (t < be) { be = t; bi = j; }           // strict < : first min
        }
        int idx = start + bi;

        float sq = fmaf(qx, qx, fmaf(qy, qy, qz * qz));
        float d  = sq + be;

        const float* cn = Cb + (size_t)(batch * NPTS + idx) * 6 + 3;
        acc = d + normal_diff2(qp + 3, cn);
    }

    __shared__ float ssum[THREADS / 32];
    float v = acc;
#pragma unroll
    for (int o = 16; o > 0; o >>= 1) v += __shfl_down_sync(0xFFFFFFFFu, v, o);
    int lane = threadIdx.x & 31, warp = threadIdx.x >> 5;
    if (lane == 0) ssum[warp] = v;
    __syncthreads();
    if (warp == 0) {
        v = (lane < THREADS / 32) ? ssum[lane] : 0.0f;
#pragma unroll
        for (int o = 4; o > 0; o >>= 1) v += __shfl_down_sync(0xFFFFFFFFu, v, o);
        if (lane == 0) g_bsum[blockIdx.x] = v;
    }
}

__global__ void __launch_bounds__(NRED) final_kernel(float* out, float inv_nq) {
    float v = g_bsum[threadIdx.x];
#pragma unroll
    for (int o = 16; o > 0; o >>= 1) v += __shfl_down_sync(0xFFFFFFFFu, v, o);
    __shared__ float ssum[NRED / 32];
    int lane = threadIdx.x & 31, warp = threadIdx.x >> 5;
    if (lane == 0) ssum[warp] = v;
    __syncthreads();
    if (warp == 0) {
        v = (lane < NRED / 32) ? ssum[lane] : 0.0f;
#pragma unroll
        for (int o = 4; o > 0; o >>= 1) v += __shfl_down_sync(0xFFFFFFFFu, v, o);
        if (lane == 0) out[0] = v * inv_nq;
    }
}

extern "C" void kernel_launch(void* const* d_in, const int* in_sizes, int n_in,
                              void* d_out, int out_size)
{
    const float* x1 = (const float*)d_in[0];
    const float* x2 = (const float*)d_in[1];
    float* out = (float*)d_out;

    int total = in_sizes[0];
    int B  = total / (NPTS * 6);      // 8
    int nq = B * NPTS;                // 32768

    dim3 grid(NCHUNK, nq / QPB, 2);   // (16, 16, 2) = 512 CTAs, one wave @ occ 4
    nn_kernel<<<grid, THREADS>>>(x1, x2);

    int rblocks = (2 * nq + THREADS - 1) / THREADS;   // 256
    merge_kernel<<<rblocks, THREADS>>>(x1, x2, nq);

    final_kernel<<<1, NRED>>>(out, 1.0f / (float)nq);
}

// round 4
// speedup vs baseline: 1.2977x; 1.2977x over previous
#include <cuda_runtime.h>
#include <cstdint>
#include <math.h>

#define NPTS    4096
#define MAXQ    32768             // B=8 * 4096
#define THREADS 256
#define QPAIRS  2                 // packed query pairs per thread (4 queries)
#define QPT     (QPAIRS * 2)
#define QPB     (THREADS * QPT)   // 1024 queries per block
#define JCHUNK  256               // candidates per block
#define NCHUNK  (NPTS / JCHUNK)   // 16
#define NGROUP  32                // argmin recovery granularity
#define NGROUPS (JCHUNK / NGROUP) // 8
#define MRBLK   2048              // merge-kernel blocks

typedef unsigned long long ull;

// Per (dir, chunk, query): (fkey(e_min) << 32) | group_start_index_within_batch
__device__ ull   g_part[2][NCHUNK][MAXQ];
__device__ float g_bsum[MRBLK];

__device__ __forceinline__ ull fma2(ull a, ull b, ull c) {
    ull d;
    asm("fma.rn.f32x2 %0, %1, %2, %3;" : "=l"(d) : "l"(a), "l"(b), "l"(c));
    return d;
}
__device__ __forceinline__ ull pack2(float lo, float hi) {
    ull d;
    asm("mov.b64 %0, {%1, %2};" : "=l"(d) : "f"(lo), "f"(hi));
    return d;
}
__device__ __forceinline__ ull dup2(float v) { return pack2(v, v); }
__device__ __forceinline__ float lof(ull v) { return __uint_as_float((unsigned int)v); }
__device__ __forceinline__ float hif(ull v) { return __uint_as_float((unsigned int)(v >> 32)); }

// Order-preserving float -> uint32 (total order incl. negatives).
__device__ __forceinline__ unsigned int fkey(float f) {
    unsigned int b = __float_as_uint(f);
    return (b & 0x80000000u) ? ~b : (b | 0x80000000u);
}

// NN kernel: per query track min over candidates of e = |c|^2 - 2<q,c>
// (argmin(e) == argmin(d)). Two queries per f32x2 lane, candidates broadcast
// from smem (uniform address). Exact index recovered later by rescanning the
// winning 32-candidate group with a bit-identical FMA chain.
__global__ void __launch_bounds__(THREADS, 5) nn_kernel(
    const float* __restrict__ X1, const float* __restrict__ X2)
{
    __shared__ ull tile[JCHUNK][4];   // per candidate: {xx, yy, zz, ww=|c|^2}

    const int dir   = blockIdx.z;              // 0: Q=X1,C=X2   1: Q=X2,C=X1
    const float* __restrict__ Q = dir ? X2 : X1;
    const float* __restrict__ C = dir ? X1 : X2;

    const int tid   = threadIdx.x;
    const int chunk = blockIdx.x;              // 0..NCHUNK-1
    const int qbase = blockIdx.y * QPB;
    const int batch = qbase / NPTS;            // QPB divides NPTS
    const int jloc  = chunk * JCHUNK;          // candidate base within batch

    {
        const float* p = C + (size_t)(batch * NPTS + jloc + tid) * 6;
        float x = p[0], y = p[1], z = p[2];
        tile[tid][0] = dup2(x);
        tile[tid][1] = dup2(y);
        tile[tid][2] = dup2(z);
        tile[tid][3] = dup2(fmaf(x, x, fmaf(y, y, z * z)));
    }
    __syncthreads();

    // Queries with -2 folded into coordinates (exact scaling).
    ull nx[QPAIRS], ny[QPAIRS], nz[QPAIRS];
    int q0[QPAIRS];
#pragma unroll
    for (int p = 0; p < QPAIRS; p++) {
        q0[p] = qbase + (p * THREADS + tid) * 2;
        const float* a = Q + (size_t)q0[p] * 6;
        const float* b = a + 6;
        nx[p] = pack2(-2.0f * a[0], -2.0f * b[0]);
        ny[p] = pack2(-2.0f * a[1], -2.0f * b[1]);
        nz[p] = pack2(-2.0f * a[2], -2.0f * b[2]);
    }

    float beste[QPT];
    int   bestg[QPT];
#pragma unroll
    for (int q = 0; q < QPT; q++) { beste[q] = 3.4e38f; bestg[q] = 0; }

    const ull* tp = &tile[0][0];
#pragma unroll 1
    for (int g = 0; g < NGROUPS; g++) {
        float gmin[QPT];
#pragma unroll
        for (int q = 0; q < QPT; q++) gmin[q] = 3.4e38f;

#pragma unroll 8
        for (int cc = 0; cc < NGROUP; cc++) {
            ulonglong2 cA = *(const ulonglong2*)(tp);       // xx, yy
            ulonglong2 cB = *(const ulonglong2*)(tp + 2);   // zz, ww
            tp += 4;
#pragma unroll
            for (int p = 0; p < QPAIRS; p++) {
                ull t = fma2(nz[p], cB.x, cB.y);            // z*cz + |c|^2
                t = fma2(ny[p], cA.y, t);
                t = fma2(nx[p], cA.x, t);                   // e for 2 queries
                gmin[2 * p]     = fminf(gmin[2 * p],     lof(t));
                gmin[2 * p + 1] = fminf(gmin[2 * p + 1], hif(t));
            }
        }
#pragma unroll
        for (int q = 0; q < QPT; q++)
            if (gmin[q] < beste[q]) { beste[q] = gmin[q]; bestg[q] = g; }
    }

#pragma unroll
    for (int p = 0; p < QPAIRS; p++) {
#pragma unroll
        for (int h = 0; h < 2; h++) {
            int qq = 2 * p + h;
            unsigned int start = (unsigned int)(jloc + bestg[qq] * NGROUP);
            g_part[dir][chunk][q0[p] + h] =
                ((ull)fkey(beste[qq]) << 32) | start;
        }
    }
}

__device__ __forceinline__ float normal_diff2(const float* __restrict__ a,
                                              const float* __restrict__ b) {
    float ax = a[0], ay = a[1], az = a[2];
    float bx = b[0], by = b[1], bz = b[2];
    float ia = 1.0f / fmaxf(sqrtf(fmaf(ax, ax, fmaf(ay, ay, az * az))), 1e-12f);
    float ib = 1.0f / fmaxf(sqrtf(fmaf(bx, bx, fmaf(by, by, bz * bz))), 1e-12f);
    float dx = ax * ia - bx * ib;
    float dy = ay * ia - by * ib;
    float dz = az * ia - bz * ib;
    return fmaf(dx, dx, fmaf(dy, dy, dz * dz));
}

// Warp-parallel merge: 8 lanes per query. Lanes cooperatively min the 16
// chunk partials (u64 min preserves first-occurrence ties), then each lane
// rescans 4 of the winning group's 32 candidates with the bit-identical
// scalar FMA chain; cross-lane argmin via packed (fkey << 32 | local_idx).
__global__ void __launch_bounds__(THREADS) merge_kernel(
    const float* __restrict__ X1, const float* __restrict__ X2, int nq)
{
    const int tid  = threadIdx.x;
    const int l    = tid & 7;                              // lane within group
    const int gi   = (blockIdx.x * THREADS + tid) >> 3;    // query slot, 0..2*nq-1
    const int dir  = gi >= nq;
    const int q    = dir ? gi - nq : gi;
    const int batch = q / NPTS;

    // 1) min over 16 chunk partials (2 per lane, then 8-lane xor reduce)
    ull best = g_part[dir][2 * l][q];
    {
        ull v = g_part[dir][2 * l + 1][q];
        best = v < best ? v : best;
    }
#pragma unroll
    for (int m = 4; m >= 1; m >>= 1) {
        ull o = __shfl_xor_sync(0xFFFFFFFFu, best, m);
        best = o < best ? o : best;
    }
    int start = (int)(best & 0xFFFFFFFFull);               // within batch

    // 2) rescan 32 candidates, 4 per lane (bit-identical chain)
    const float* __restrict__ Qb = dir ? X2 : X1;
    const float* __restrict__ Cb = dir ? X1 : X2;
    const float* qp = Qb + (size_t)q * 6;
    float qx = qp[0], qy = qp[1], qz = qp[2];
    float nxs = -2.0f * qx, nys = -2.0f * qy, nzs = -2.0f * qz;

    const float* cbase = Cb + (size_t)(batch * NPTS + start + l * 4) * 6;
    float be = 3.4e38f;
    int   bi = 0;
#pragma unroll
    for (int j = 0; j < 4; j++) {
        const float* c = cbase + j * 6;
        float cx = c[0], cy = c[1], cz = c[2];
        float cw = fmaf(cx, cx, fmaf(cy, cy, cz * cz));
        float t  = fmaf(nxs, cx, fmaf(nys, cy, fmaf(nzs, cz, cw)));
        if (t < be) { be = t; bi = j; }                    // strict <: first min
    }
    ull bk = ((ull)fkey(be) << 32) | (unsigned int)(l * 4 + bi);
#pragma unroll
    for (int m = 4; m >= 1; m >>= 1) {
        ull o = __shfl_xor_sync(0xFFFFFFFFu, bk, m);
        bk = o < bk ? o : bk;                              // tie -> smaller idx
    }

    // 3) lane 0 computes the per-query contribution
    float acc = 0.0f;
    if (l == 0) {
        int idx = start + (int)(bk & 31u);
        unsigned int ek = (unsigned int)(bk >> 32);
        float e = __uint_as_float((ek & 0x80000000u) ? (ek & 0x7FFFFFFFu) : ~ek);
        float sq = fmaf(qx, qx, fmaf(qy, qy, qz * qz));
        const float* cn = Cb + (size_t)(batch * NPTS + idx) * 6 + 3;
        acc = (sq + e) + normal_diff2(qp + 3, cn);
    }

    // block reduction
    __shared__ float ssum[THREADS / 32];
    float v = acc;
#pragma unroll
    for (int o = 16; o > 0; o >>= 1) v += __shfl_down_sync(0xFFFFFFFFu, v, o);
    int lane = tid & 31, warp = tid >> 5;
    if (lane == 0) ssum[warp] = v;
    __syncthreads();
    if (warp == 0) {
        v = (lane < THREADS / 32) ? ssum[lane] : 0.0f;
#pragma unroll
        for (int o = 4; o > 0; o >>= 1) v += __shfl_down_sync(0xFFFFFFFFu, v, o);
        if (lane == 0) g_bsum[blockIdx.x] = v;
    }
}

__global__ void __launch_bounds__(THREADS) final_kernel(float* out, float inv_nq) {
    float v = 0.0f;
#pragma unroll
    for (int i = 0; i < MRBLK / THREADS; i++)
        v += g_bsum[threadIdx.x + i * THREADS];
#pragma unroll
    for (int o = 16; o > 0; o >>= 1) v += __shfl_down_sync(0xFFFFFFFFu, v, o);
    __shared__ float ssum[THREADS / 32];
    int lane = threadIdx.x & 31, warp = threadIdx.x >> 5;
    if (lane == 0) ssum[warp] = v;
    __syncthreads();
    if (warp == 0) {
        v = (lane < THREADS / 32) ? ssum[lane] : 0.0f;
#pragma unroll
        for (int o = 4; o > 0; o >>= 1) v += __shfl_down_sync(0xFFFFFFFFu, v, o);
        if (lane == 0) out[0] = v * inv_nq;
    }
}

extern "C" void kernel_launch(void* const* d_in, const int* in_sizes, int n_in,
                              void* d_out, int out_size)
{
    const float* x1 = (const float*)d_in[0];
    const float* x2 = (const float*)d_in[1];
    float* out = (float*)d_out;

    int total = in_sizes[0];
    int B  = total / (NPTS * 6);      // 8
    int nq = B * NPTS;                // 32768

    dim3 grid(NCHUNK, nq / QPB, 2);   // (16, 32, 2) = 1024 CTAs
    nn_kernel<<<grid, THREADS>>>(x1, x2);

    // 2*nq queries * 8 lanes / 256 threads = 2048 blocks
    merge_kernel<<<MRBLK, THREADS>>>(x1, x2, nq);

    final_kernel<<<1, THREADS>>>(out, 1.0f / (float)nq);
}

// round 5
// speedup vs baseline: 1.3457x; 1.0370x over previous
#include <cuda_runtime.h>
#include <cstdint>
#include <math.h>

#define NPTS    4096
#define MAXQ    32768             // B=8 * 4096
#define THREADS 256
#define QPT     4                 // queries per thread
#define QPB     (THREADS * QPT)   // 1024 queries per block
#define JCHUNK  512               // candidates per block
#define NCHUNK  (NPTS / JCHUNK)   // 8
#define NGROUP  32                // argmin recovery granularity
#define NGROUPS (JCHUNK / NGROUP) // 16
#define MRBLK   2048              // merge-kernel blocks

typedef unsigned long long ull;

// Per (dir, chunk, query): (fkey(e_min) << 32) | group_start_index_within_batch
__device__ ull   g_part[2][NCHUNK][MAXQ];
__device__ float g_bsum[MRBLK];

__device__ __forceinline__ ull fma2(ull a, ull b, ull c) {
    ull d;
    asm("fma.rn.f32x2 %0, %1, %2, %3;" : "=l"(d) : "l"(a), "l"(b), "l"(c));
    return d;
}
__device__ __forceinline__ ull dup2(float v) {
    ull d;
    asm("mov.b64 %0, {%1, %1};" : "=l"(d) : "f"(v));
    return d;
}
__device__ __forceinline__ float lof(ull v) { return __uint_as_float((unsigned int)v); }
__device__ __forceinline__ float hif(ull v) { return __uint_as_float((unsigned int)(v >> 32)); }

// Order-preserving float -> uint32 (total order incl. negatives).
__device__ __forceinline__ unsigned int fkey(float f) {
    unsigned int b = __float_as_uint(f);
    return (b & 0x80000000u) ? ~b : (b | 0x80000000u);
}

// NN kernel: per query, min over candidates of e = |c|^2 - 2<q,c>
// (argmin(e) == argmin(d)). Candidates packed 2-per-f32x2 from an SoA smem
// tile (1 LDS.128 = 4 candidates per coordinate array); queries duplicated
// into both f32x2 lanes once, outside the loop. Exact index recovered later
// by rescanning the winning 32-candidate group with a bit-identical chain.
__global__ void __launch_bounds__(THREADS, 4) nn_kernel(
    const float* __restrict__ X1, const float* __restrict__ X2)
{
    __shared__ __align__(16) float sX[JCHUNK];
    __shared__ __align__(16) float sY[JCHUNK];
    __shared__ __align__(16) float sZ[JCHUNK];
    __shared__ __align__(16) float sW[JCHUNK];

    const int dir   = blockIdx.z;              // 0: Q=X1,C=X2   1: Q=X2,C=X1
    const float* __restrict__ Q = dir ? X2 : X1;
    const float* __restrict__ C = dir ? X1 : X2;

    const int tid   = threadIdx.x;
    const int chunk = blockIdx.x;              // 0..NCHUNK-1
    const int qbase = blockIdx.y * QPB;
    const int batch = qbase / NPTS;            // QPB divides NPTS
    const int jloc  = chunk * JCHUNK;          // candidate base within batch

    // Stage candidate slice as SoA {x, y, z, |c|^2}
#pragma unroll
    for (int s = 0; s < JCHUNK / THREADS; s++) {
        int j = tid + s * THREADS;
        const float* p = C + (size_t)(batch * NPTS + jloc + j) * 6;
        float x = p[0], y = p[1], z = p[2];
        sX[j] = x; sY[j] = y; sZ[j] = z;
        sW[j] = fmaf(x, x, fmaf(y, y, z * z));
    }
    __syncthreads();

    // Queries: -2 folded in (exact), duplicated into both f32x2 lanes.
    ull qx[QPT], qy[QPT], qz[QPT];
#pragma unroll
    for (int k = 0; k < QPT; k++) {
        const float* a = Q + (size_t)(qbase + k * THREADS + tid) * 6;
        qx[k] = dup2(-2.0f * a[0]);
        qy[k] = dup2(-2.0f * a[1]);
        qz[k] = dup2(-2.0f * a[2]);
    }

    float beste[QPT];
    int   bestg[QPT];
#pragma unroll
    for (int k = 0; k < QPT; k++) { beste[k] = 3.4e38f; bestg[k] = 0; }

    const ulonglong2* __restrict__ pX = (const ulonglong2*)sX;
    const ulonglong2* __restrict__ pY = (const ulonglong2*)sY;
    const ulonglong2* __restrict__ pZ = (const ulonglong2*)sZ;
    const ulonglong2* __restrict__ pW = (const ulonglong2*)sW;

#pragma unroll 1
    for (int g = 0; g < NGROUPS; g++) {
        float g0[QPT], g1[QPT];
#pragma unroll
        for (int k = 0; k < QPT; k++) { g0[k] = 3.4e38f; g1[k] = 3.4e38f; }

#pragma unroll 4
        for (int qq = 0; qq < NGROUP / 4; qq++) {       // quads of candidates
            int qd = g * (NGROUP / 4) + qq;
            ulonglong2 xs = pX[qd];                      // (x0,x1),(x2,x3)
            ulonglong2 ys = pY[qd];
            ulonglong2 zs = pZ[qd];
            ulonglong2 ws = pW[qd];
#pragma unroll
            for (int k = 0; k < QPT; k++) {
                ull t = fma2(qz[k], zs.x, ws.x);
                t = fma2(qy[k], ys.x, t);
                t = fma2(qx[k], xs.x, t);                // e for cand 0,1
                g0[k] = fminf(g0[k], lof(t));
                g1[k] = fminf(g1[k], hif(t));
                ull u = fma2(qz[k], zs.y, ws.y);
                u = fma2(qy[k], ys.y, u);
                u = fma2(qx[k], xs.y, u);                // e for cand 2,3
                g0[k] = fminf(g0[k], lof(u));
                g1[k] = fminf(g1[k], hif(u));
            }
        }
#pragma unroll
        for (int k = 0; k < QPT; k++) {
            float gm = fminf(g0[k], g1[k]);
            if (gm < beste[k]) { beste[k] = gm; bestg[k] = g; }
        }
    }

#pragma unroll
    for (int k = 0; k < QPT; k++) {
        unsigned int start = (unsigned int)(jloc + bestg[k] * NGROUP);
        g_part[dir][chunk][qbase + k * THREADS + tid] =
            ((ull)fkey(beste[k]) << 32) | start;
    }
}

__device__ __forceinline__ float normal_diff2(const float* __restrict__ a,
                                              const float* __restrict__ b) {
    float ax = a[0], ay = a[1], az = a[2];
    float bx = b[0], by = b[1], bz = b[2];
    float ia = 1.0f / fmaxf(sqrtf(fmaf(ax, ax, fmaf(ay, ay, az * az))), 1e-12f);
    float ib = 1.0f / fmaxf(sqrtf(fmaf(bx, bx, fmaf(by, by, bz * bz))), 1e-12f);
    float dx = ax * ia - bx * ib;
    float dy = ay * ia - by * ib;
    float dz = az * ia - bz * ib;
    return fmaf(dx, dx, fmaf(dy, dy, dz * dz));
}

// Warp-parallel merge: 8 lanes per query, one chunk-partial per lane.
// u64 min preserves first-occurrence ties; each lane rescans 4 of the
// winning group's 32 candidates with the bit-identical scalar FMA chain.
__global__ void __launch_bounds__(THREADS) merge_kernel(
    const float* __restrict__ X1, const float* __restrict__ X2, int nq)
{
    const int tid  = threadIdx.x;
    const int l    = tid & 7;                              // lane within group
    const int gi   = (blockIdx.x * THREADS + tid) >> 3;    // query slot
    const int dir  = gi >= nq;
    const int q    = dir ? gi - nq : gi;
    const int batch = q / NPTS;

    // 1) min over NCHUNK=8 partials (1 per lane, 8-lane xor reduce)
    ull best = g_part[dir][l][q];
#pragma unroll
    for (int m = 4; m >= 1; m >>= 1) {
        ull o = __shfl_xor_sync(0xFFFFFFFFu, best, m);
        best = o < best ? o : best;
    }
    int start = (int)(best & 0xFFFFFFFFull);               // within batch

    // 2) rescan 32 candidates, 4 per lane, high-MLP float2 loads
    const float* __restrict__ Qb = dir ? X2 : X1;
    const float* __restrict__ Cb = dir ? X1 : X2;
    const float* qp = Qb + (size_t)q * 6;
    float qx = qp[0], qy = qp[1], qz = qp[2];
    float nxs = -2.0f * qx, nys = -2.0f * qy, nzs = -2.0f * qz;

    const float2* cb2 = (const float2*)(Cb + (size_t)(batch * NPTS + start + l * 4) * 6);
    float2 f0[4], f1[4], f2[4];
#pragma unroll
    for (int j = 0; j < 4; j++) {           // 12 independent LDG.64
        f0[j] = cb2[j * 3 + 0];             // x, y
        f1[j] = cb2[j * 3 + 1];             // z, nx
        f2[j] = cb2[j * 3 + 2];             // ny, nz (unused here)
    }
    float be = 3.4e38f;
    int   bi = 0;
#pragma unroll
    for (int j = 0; j < 4; j++) {
        float cx = f0[j].x, cy = f0[j].y, cz = f1[j].x;
        float cw = fmaf(cx, cx, fmaf(cy, cy, cz * cz));
        float t  = fmaf(nxs, cx, fmaf(nys, cy, fmaf(nzs, cz, cw)));
        if (t < be) { be = t; bi = j; }                    // strict <: first min
    }
    ull bk = ((ull)fkey(be) << 32) | (unsigned int)(l * 4 + bi);
#pragma unroll
    for (int m = 4; m >= 1; m >>= 1) {
        ull o = __shfl_xor_sync(0xFFFFFFFFu, bk, m);
        bk = o < bk ? o : bk;                              // tie -> smaller idx
    }

    // 3) lane 0 computes the per-query contribution
    float acc = 0.0f;
    if (l == 0) {
        int idx = start + (int)(bk & 31u);
        unsigned int ek = (unsigned int)(bk >> 32);
        float e = __uint_as_float((ek & 0x80000000u) ? (ek & 0x7FFFFFFFu) : ~ek);
        float sq = fmaf(qx, qx, fmaf(qy, qy, qz * qz));
        const float* cn = Cb + (size_t)(batch * NPTS + idx) * 6 + 3;
        acc = (sq + e) + normal_diff2(qp + 3, cn);
    }

    __shared__ float ssum[THREADS / 32];
    float v = acc;
#pragma unroll
    for (int o = 16; o > 0; o >>= 1) v += __shfl_down_sync(0xFFFFFFFFu, v, o);
    int lane = tid & 31, warp = tid >> 5;
    if (lane == 0) ssum[warp] = v;
    __syncthreads();
    if (warp == 0) {
        v = (lane < THREADS / 32) ? ssum[lane] : 0.0f;
#pragma unroll
        for (int o = 4; o > 0; o >>= 1) v += __shfl_down_sync(0xFFFFFFFFu, v, o);
        if (lane == 0) g_bsum[blockIdx.x] = v;
    }
}

__global__ void __launch_bounds__(THREADS) final_kernel(float* out, float inv_nq) {
    float v = 0.0f;
#pragma unroll
    for (int i = 0; i < MRBLK / THREADS; i++)
        v += g_bsum[threadIdx.x + i * THREADS];
#pragma unroll
    for (int o = 16; o > 0; o >>= 1) v += __shfl_down_sync(0xFFFFFFFFu, v, o);
    __shared__ float ssum[THREADS / 32];
    int lane = threadIdx.x & 31, warp = threadIdx.x >> 5;
    if (lane == 0) ssum[warp] = v;
    __syncthreads();
    if (warp == 0) {
        v = (lane < THREADS / 32) ? ssum[lane] : 0.0f;
#pragma unroll
        for (int o = 4; o > 0; o >>= 1) v += __shfl_down_sync(0xFFFFFFFFu, v, o);
        if (lane == 0) out[0] = v * inv_nq;
    }
}

extern "C" void kernel_launch(void* const* d_in, const int* in_sizes, int n_in,
                              void* d_out, int out_size)
{
    const float* x1 = (const float*)d_in[0];
    const float* x2 = (const float*)d_in[1];
    float* out = (float*)d_out;

    int total = in_sizes[0];
    int B  = total / (NPTS * 6);      // 8
    int nq = B * NPTS;                // 32768

    dim3 grid(NCHUNK, nq / QPB, 2);   // (8, 32, 2) = 512 CTAs, one wave @ occ 4
    nn_kernel<<<grid, THREADS>>>(x1, x2);

    // 2*nq queries * 8 lanes / 256 threads = 2048 blocks
    merge_kernel<<<MRBLK, THREADS>>>(x1, x2, nq);

    final_kernel<<<1, THREADS>>>(out, 1.0f / (float)nq);
}